// round 5
// baseline (speedup 1.0000x reference)
#include <cuda_runtime.h>
#include <cuda_bf16.h>
#include <cstdint>

#define NB  8
#define EHD 768
#define TD  512
#define PHD 320
#define UD  128
#define JHD 320
#define NC  34
#define NCPAD 40           // 5 n-tiles of 8

typedef unsigned long long ull;

// Scratch (allocation-free rule: device globals)
__device__ float g_e[NB * TD * JHD];            // (B, T, JH)
__device__ float g_p[NB * UD * JHD];            // (B, U, JH)
__device__ __nv_bfloat16 g_whi[NCPAD * JHD];    // W_out split hi (c-major)
__device__ __nv_bfloat16 g_wlo[NCPAD * JHD];    // W_out split lo

// ---------------- f32x2 helpers (proj kernels) ----------------
static __device__ __forceinline__ ull pack2(float x, float y) {
    ull r;
    asm("mov.b64 %0, {%1, %2};" : "=l"(r) : "f"(x), "f"(y));
    return r;
}
static __device__ __forceinline__ void unpack2(ull v, float& x, float& y) {
    asm("mov.b64 {%0, %1}, %2;" : "=f"(x), "=f"(y) : "l"(v));
}
static __device__ __forceinline__ void ffma2(ull& acc, ull a, ull b) {
    asm("fma.rn.f32x2 %0, %1, %2, %0;" : "+l"(acc) : "l"(a), "l"(b));
}

// bf16x2 pack: lower half <- a (even/first element), upper half <- b
static __device__ __forceinline__ uint32_t pack_bf16x2(float a, float b) {
    uint32_t r;
    asm("cvt.rn.bf16x2.f32 %0, %1, %2;" : "=r"(r) : "f"(b), "f"(a));
    return r;
}

// mma.sync m16n8k16 row.col f32.bf16.bf16.f32
static __device__ __forceinline__ void mma16816(float* d, uint32_t a0, uint32_t a1,
                                                uint32_t a2, uint32_t a3,
                                                uint32_t b0, uint32_t b1) {
    asm volatile(
        "mma.sync.aligned.m16n8k16.row.col.f32.bf16.bf16.f32 "
        "{%0,%1,%2,%3}, {%4,%5,%6,%7}, {%8,%9}, {%0,%1,%2,%3};"
        : "+f"(d[0]), "+f"(d[1]), "+f"(d[2]), "+f"(d[3])
        : "r"(a0), "r"(a1), "r"(a2), "r"(a3), "r"(b0), "r"(b1));
}

// ---------------- W_out pre-split kernel ----------------
__global__ void prep_w_kernel(const float* __restrict__ Wo) {
    const int c = blockIdx.x;      // 0..39
    const int j = threadIdx.x;     // 0..319
    float w = (c < NC) ? Wo[c * JHD + j] : 0.f;
    __nv_bfloat16 hi = __float2bfloat16(w);
    __nv_bfloat16 lo = __float2bfloat16(w - __bfloat162float(hi));
    g_whi[c * JHD + j] = hi;
    g_wlo[c * JHD + j] = lo;
}

// ---------------- merged projection GEMM ----------------
// out[b,l,j] = sum_h X[b,h,l] * W[j,h] + bias[j]
// Tile 32 l x 64 j, 128 threads, 4x4 microtile, register double-buffered gmem.
__global__ __launch_bounds__(128) void proj_all_kernel(
    const float* __restrict__ enc, const float* __restrict__ W_enc,
    const float* __restrict__ b_enc,
    const float* __restrict__ dec, const float* __restrict__ W_pred,
    const float* __restrict__ b_pred,
    float* __restrict__ e_out, float* __restrict__ p_out)
{
    __shared__ float Xs[16][36];
    __shared__ float Ws[16][68];

    const float* X; const float* W; const float* bias; float* out;
    int H, L, l0;
    if (blockIdx.x < 16) {
        X = enc; W = W_enc; bias = b_enc; out = e_out;
        H = EHD; L = TD; l0 = blockIdx.x * 32;
    } else {
        X = dec; W = W_pred; bias = b_pred; out = p_out;
        H = PHD; L = UD; l0 = (blockIdx.x - 16) * 32;
    }
    const int b  = blockIdx.z;
    const int j0 = blockIdx.y * 64;
    const int tid = threadIdx.x;
    const int tl = tid & 7;
    const int tj = tid >> 3;

    ull acc[4][2];
#pragma unroll
    for (int m = 0; m < 4; m++) { acc[m][0] = 0ull; acc[m][1] = 0ull; }

    const int kkL = tid >> 3, vL = tid & 7;
    const int jjW = tid >> 1, hsel = (tid & 1) * 2;

    const float* Xg = X + ((size_t)b * H + kkL) * L + l0 + vL * 4;
    const float* Wg = W + (size_t)(j0 + jjW) * H;

    float4 xv = *(const float4*)(Xg);
    float4 wv0 = *(const float4*)(Wg + (hsel + 0) * 4);
    float4 wv1 = *(const float4*)(Wg + (hsel + 1) * 4);

    for (int h0 = 0; h0 < H; h0 += 16) {
        *(float4*)&Xs[kkL][vL * 4] = xv;
        Ws[(hsel + 0) * 4 + 0][jjW] = wv0.x;
        Ws[(hsel + 0) * 4 + 1][jjW] = wv0.y;
        Ws[(hsel + 0) * 4 + 2][jjW] = wv0.z;
        Ws[(hsel + 0) * 4 + 3][jjW] = wv0.w;
        Ws[(hsel + 1) * 4 + 0][jjW] = wv1.x;
        Ws[(hsel + 1) * 4 + 1][jjW] = wv1.y;
        Ws[(hsel + 1) * 4 + 2][jjW] = wv1.z;
        Ws[(hsel + 1) * 4 + 3][jjW] = wv1.w;
        __syncthreads();
        if (h0 + 16 < H) {
            xv  = *(const float4*)(Xg + (size_t)(h0 + 16) * L);
            wv0 = *(const float4*)(Wg + h0 + 16 + (hsel + 0) * 4);
            wv1 = *(const float4*)(Wg + h0 + 16 + (hsel + 1) * 4);
        }
#pragma unroll
        for (int kk = 0; kk < 16; kk++) {
            ulonglong2 ap = *(const ulonglong2*)&Xs[kk][tl * 4];
            float4 wq = *(const float4*)&Ws[kk][tj * 4];
            ull w0 = pack2(wq.x, wq.x);
            ull w1 = pack2(wq.y, wq.y);
            ull w2 = pack2(wq.z, wq.z);
            ull w3 = pack2(wq.w, wq.w);
            ffma2(acc[0][0], w0, ap.x); ffma2(acc[0][1], w0, ap.y);
            ffma2(acc[1][0], w1, ap.x); ffma2(acc[1][1], w1, ap.y);
            ffma2(acc[2][0], w2, ap.x); ffma2(acc[2][1], w2, ap.y);
            ffma2(acc[3][0], w3, ap.x); ffma2(acc[3][1], w3, ap.y);
        }
        __syncthreads();
    }

    float4 bi = *(const float4*)(bias + j0 + tj * 4);
#pragma unroll
    for (int pp = 0; pp < 2; pp++) {
        float a0x, a0y, a1x, a1y, a2x, a2y, a3x, a3y;
        unpack2(acc[0][pp], a0x, a0y);
        unpack2(acc[1][pp], a1x, a1y);
        unpack2(acc[2][pp], a2x, a2y);
        unpack2(acc[3][pp], a3x, a3y);
        const int l = l0 + tl * 4 + pp * 2;
        float4 o0 = make_float4(a0x + bi.x, a1x + bi.y, a2x + bi.z, a3x + bi.w);
        float4 o1 = make_float4(a0y + bi.x, a1y + bi.y, a2y + bi.z, a3y + bi.w);
        *(float4*)(out + ((size_t)b * L + l    ) * JHD + j0 + tj * 4) = o0;
        *(float4*)(out + ((size_t)b * L + l + 1) * JHD + j0 + tj * 4) = o1;
    }
}

// ---------------- joint kernel: mma.sync bf16 split ----------------
// CTA 128 thr (4 warps): b, 4 t, 64 u (warp = 16 u), 40 classes, K=320.
// D = relu(e+p) @ Wo^T via Ahi*Bhi + Ahi*Blo + Alo*Bhi, fp32 accum.
#define PSTR 324
#define JS_P (64 * PSTR)          // f32
#define JS_E (4 * JHD)
#define JS_TOTAL ((JS_P + JS_E) * 4)

__global__ __launch_bounds__(128, 2) void joint_mma_kernel(
    const float* __restrict__ e, const float* __restrict__ p,
    const __nv_bfloat16* __restrict__ whi, const __nv_bfloat16* __restrict__ wlo,
    const float* __restrict__ bo, float* __restrict__ out)
{
    extern __shared__ float sm[];
    float* p_s = sm;               // [64][PSTR]
    float* e_s = sm + JS_P;        // [4][320]

    const int tid = threadIdx.x;
    const int wid = tid >> 5;
    const int lane = tid & 31;
    const int g = lane >> 2;       // 0..7
    const int tig = lane & 3;      // 0..3
    const int b    = blockIdx.z;
    const int tg   = blockIdx.y * 4;
    const int ublk = blockIdx.x;   // 0..1

    // load p tile (64 u rows)
    {
        const float* pb = p + ((size_t)b * UD + ublk * 64) * JHD;
        for (int idx = tid; idx < 64 * 80; idx += 128) {
            int r = idx / 80, q = idx - r * 80;
            float4 v = *(const float4*)(pb + r * JHD + q * 4);
            *(float4*)&p_s[r * PSTR + q * 4] = v;
        }
    }
    // load e tile (4 t rows)
    {
        const float* eb = e + ((size_t)b * TD + tg) * JHD;
        for (int idx = tid; idx < 4 * 80; idx += 128) {
            float4 v = *(const float4*)(eb + idx * 4);
            *(float4*)&e_s[idx * 4] = v;
        }
    }
    // bias for this lane's 10 classes
    float bv[10];
#pragma unroll
    for (int nt = 0; nt < 5; nt++) {
        int c = nt * 8 + 2 * tig;
        bv[2 * nt]     = (c     < NC) ? bo[c]     : 0.f;
        bv[2 * nt + 1] = (c + 1 < NC) ? bo[c + 1] : 0.f;
    }
    __syncthreads();

    float acc[4][5][4];
#pragma unroll
    for (int ti = 0; ti < 4; ti++)
#pragma unroll
        for (int nt = 0; nt < 5; nt++)
#pragma unroll
            for (int r = 0; r < 4; r++) acc[ti][nt][r] = 0.f;

    const int r0 = wid * 16 + g;   // u-local row (second row = r0+8)

#pragma unroll 1
    for (int k0 = 0; k0 < JHD; k0 += 16) {
        const int jA = k0 + 2 * tig;
        const int jB = jA + 8;

        // B fragments (register-cached, reused across 4 t)
        uint32_t bh0[5], bh1[5], bl0[5], bl1[5];
#pragma unroll
        for (int nt = 0; nt < 5; nt++) {
            int c = nt * 8 + g;
            bh0[nt] = *(const uint32_t*)(whi + c * JHD + jA);
            bh1[nt] = *(const uint32_t*)(whi + c * JHD + jB);
            bl0[nt] = *(const uint32_t*)(wlo + c * JHD + jA);
            bl1[nt] = *(const uint32_t*)(wlo + c * JHD + jB);
        }

#pragma unroll
        for (int ti = 0; ti < 4; ti++) {
            float2 ev0 = *(const float2*)&e_s[ti * JHD + jA];
            float2 ev1 = *(const float2*)&e_s[ti * JHD + jB];
            float2 p00 = *(const float2*)&p_s[r0 * PSTR + jA];
            float2 p01 = *(const float2*)&p_s[r0 * PSTR + jB];
            float2 p10 = *(const float2*)&p_s[(r0 + 8) * PSTR + jA];
            float2 p11 = *(const float2*)&p_s[(r0 + 8) * PSTR + jB];

            // h values: a0=(r0,jA) a1=(r0+8,jA) a2=(r0,jB) a3=(r0+8,jB)
            float h0x = fmaxf(ev0.x + p00.x, 0.f), h0y = fmaxf(ev0.y + p00.y, 0.f);
            float h1x = fmaxf(ev0.x + p10.x, 0.f), h1y = fmaxf(ev0.y + p10.y, 0.f);
            float h2x = fmaxf(ev1.x + p01.x, 0.f), h2y = fmaxf(ev1.y + p01.y, 0.f);
            float h3x = fmaxf(ev1.x + p11.x, 0.f), h3y = fmaxf(ev1.y + p11.y, 0.f);

            uint32_t a0h = pack_bf16x2(h0x, h0y);
            uint32_t a1h = pack_bf16x2(h1x, h1y);
            uint32_t a2h = pack_bf16x2(h2x, h2y);
            uint32_t a3h = pack_bf16x2(h3x, h3y);

            uint32_t a0l = pack_bf16x2(h0x - __uint_as_float(a0h << 16),
                                       h0y - __uint_as_float(a0h & 0xFFFF0000u));
            uint32_t a1l = pack_bf16x2(h1x - __uint_as_float(a1h << 16),
                                       h1y - __uint_as_float(a1h & 0xFFFF0000u));
            uint32_t a2l = pack_bf16x2(h2x - __uint_as_float(a2h << 16),
                                       h2y - __uint_as_float(a2h & 0xFFFF0000u));
            uint32_t a3l = pack_bf16x2(h3x - __uint_as_float(a3h << 16),
                                       h3y - __uint_as_float(a3h & 0xFFFF0000u));

#pragma unroll
            for (int nt = 0; nt < 5; nt++) {
                mma16816(acc[ti][nt], a0h, a1h, a2h, a3h, bh0[nt], bh1[nt]);
                mma16816(acc[ti][nt], a0h, a1h, a2h, a3h, bl0[nt], bl1[nt]);
                mma16816(acc[ti][nt], a0l, a1l, a2l, a3l, bh0[nt], bh1[nt]);
            }
        }
    }

    // ---- epilogue: bias + log_softmax (quad shuffle) + store ----
#pragma unroll 1
    for (int ti = 0; ti < 4; ti++) {
#pragma unroll
        for (int rowsel = 0; rowsel < 2; rowsel++) {
            float lv[10];
#pragma unroll
            for (int nt = 0; nt < 5; nt++) {
                lv[2 * nt]     = acc[ti][nt][2 * rowsel]     + bv[2 * nt];
                lv[2 * nt + 1] = acc[ti][nt][2 * rowsel + 1] + bv[2 * nt + 1];
            }
            float m = -3.402823466e38f;
#pragma unroll
            for (int i = 0; i < 8; i++) m = fmaxf(m, lv[i]);
            if (tig == 0) { m = fmaxf(m, lv[8]); m = fmaxf(m, lv[9]); }
            m = fmaxf(m, __shfl_xor_sync(0xFFFFFFFFu, m, 1));
            m = fmaxf(m, __shfl_xor_sync(0xFFFFFFFFu, m, 2));
            float s = 0.f;
#pragma unroll
            for (int i = 0; i < 8; i++) s += __expf(lv[i] - m);
            if (tig == 0) { s += __expf(lv[8] - m); s += __expf(lv[9] - m); }
            s += __shfl_xor_sync(0xFFFFFFFFu, s, 1);
            s += __shfl_xor_sync(0xFFFFFFFFu, s, 2);
            const float lse = m + __logf(s);

            const int u = ublk * 64 + r0 + rowsel * 8;
            float* op = out + (((size_t)b * TD + tg + ti) * UD + u) * NC;
#pragma unroll
            for (int nt = 0; nt < 4; nt++)
                *(float2*)(op + nt * 8 + 2 * tig) =
                    make_float2(lv[2 * nt] - lse, lv[2 * nt + 1] - lse);
            if (tig == 0)
                *(float2*)(op + 32) = make_float2(lv[8] - lse, lv[9] - lse);
        }
    }
}

// ---------------- launch ----------------
extern "C" void kernel_launch(void* const* d_in, const int* in_sizes, int n_in,
                              void* d_out, int out_size)
{
    const float* enc    = (const float*)d_in[0];
    const float* dec    = (const float*)d_in[1];
    const float* W_enc  = (const float*)d_in[2];
    const float* b_enc  = (const float*)d_in[3];
    const float* W_pred = (const float*)d_in[4];
    const float* b_pred = (const float*)d_in[5];
    const float* W_out  = (const float*)d_in[6];
    const float* b_out  = (const float*)d_in[7];
    float* out = (float*)d_out;

    float *e_buf = nullptr, *p_buf = nullptr;
    __nv_bfloat16 *whi = nullptr, *wlo = nullptr;
    cudaGetSymbolAddress((void**)&e_buf, g_e);
    cudaGetSymbolAddress((void**)&p_buf, g_p);
    cudaGetSymbolAddress((void**)&whi, g_whi);
    cudaGetSymbolAddress((void**)&wlo, g_wlo);

    cudaFuncSetAttribute(joint_mma_kernel,
                         cudaFuncAttributeMaxDynamicSharedMemorySize, JS_TOTAL);

    prep_w_kernel<<<NCPAD, JHD>>>(W_out);
    proj_all_kernel<<<dim3(20, 5, NB), 128>>>(enc, W_enc, b_enc,
                                              dec, W_pred, b_pred, e_buf, p_buf);
    joint_mma_kernel<<<dim3(2, TD / 4, NB), 128, JS_TOTAL>>>(
        e_buf, p_buf, whi, wlo, b_out, out);
}

// round 6
// speedup vs baseline: 1.1872x; 1.1872x over previous
#include <cuda_runtime.h>
#include <cuda_bf16.h>
#include <cstdint>

#define NB  8
#define EHD 768
#define TD  512
#define PHD 320
#define UD  128
#define JHD 320
#define NC  34
#define WST 36            // padded class stride (144B rows, 16B aligned)

typedef unsigned long long ull;

// Scratch (allocation-free rule: device globals)
__device__ float g_e[NB * TD * JHD];    // (B, T, JH)
__device__ float g_p[NB * UD * JHD];    // (B, U, JH)
__device__ float g_wt[JHD * WST];       // W_out transposed [j][c], padded

// ---------------- f32x2 helpers ----------------
static __device__ __forceinline__ ull pack2(float x, float y) {
    ull r;
    asm("mov.b64 %0, {%1, %2};" : "=l"(r) : "f"(x), "f"(y));
    return r;
}
static __device__ __forceinline__ void unpack2(ull v, float& x, float& y) {
    asm("mov.b64 {%0, %1}, %2;" : "=f"(x), "=f"(y) : "l"(v));
}
static __device__ __forceinline__ void ffma2(ull& acc, ull a, ull b) {
    asm("fma.rn.f32x2 %0, %1, %2, %0;" : "+l"(acc) : "l"(a), "l"(b));
}

// ---------------- W_out transpose prep ----------------
__global__ void prep_w_kernel(const float* __restrict__ Wo) {
    int idx = blockIdx.x * blockDim.x + threadIdx.x;   // 0..11519
    if (idx >= JHD * WST) return;
    int j = idx / WST, c = idx - j * WST;
    g_wt[idx] = (c < NC) ? Wo[c * JHD + j] : 0.f;
}

// ---------------- merged projection GEMM (R5, double-buffered) ----------------
__global__ __launch_bounds__(128) void proj_all_kernel(
    const float* __restrict__ enc, const float* __restrict__ W_enc,
    const float* __restrict__ b_enc,
    const float* __restrict__ dec, const float* __restrict__ W_pred,
    const float* __restrict__ b_pred,
    float* __restrict__ e_out, float* __restrict__ p_out)
{
    __shared__ float Xs[16][36];
    __shared__ float Ws[16][68];

    const float* X; const float* W; const float* bias; float* out;
    int H, L, l0;
    if (blockIdx.x < 16) {
        X = enc; W = W_enc; bias = b_enc; out = e_out;
        H = EHD; L = TD; l0 = blockIdx.x * 32;
    } else {
        X = dec; W = W_pred; bias = b_pred; out = p_out;
        H = PHD; L = UD; l0 = (blockIdx.x - 16) * 32;
    }
    const int b  = blockIdx.z;
    const int j0 = blockIdx.y * 64;
    const int tid = threadIdx.x;
    const int tl = tid & 7;
    const int tj = tid >> 3;

    ull acc[4][2];
#pragma unroll
    for (int m = 0; m < 4; m++) { acc[m][0] = 0ull; acc[m][1] = 0ull; }

    const int kkL = tid >> 3, vL = tid & 7;
    const int jjW = tid >> 1, hsel = (tid & 1) * 2;

    const float* Xg = X + ((size_t)b * H + kkL) * L + l0 + vL * 4;
    const float* Wg = W + (size_t)(j0 + jjW) * H;

    float4 xv = *(const float4*)(Xg);
    float4 wv0 = *(const float4*)(Wg + (hsel + 0) * 4);
    float4 wv1 = *(const float4*)(Wg + (hsel + 1) * 4);

    for (int h0 = 0; h0 < H; h0 += 16) {
        *(float4*)&Xs[kkL][vL * 4] = xv;
        Ws[(hsel + 0) * 4 + 0][jjW] = wv0.x;
        Ws[(hsel + 0) * 4 + 1][jjW] = wv0.y;
        Ws[(hsel + 0) * 4 + 2][jjW] = wv0.z;
        Ws[(hsel + 0) * 4 + 3][jjW] = wv0.w;
        Ws[(hsel + 1) * 4 + 0][jjW] = wv1.x;
        Ws[(hsel + 1) * 4 + 1][jjW] = wv1.y;
        Ws[(hsel + 1) * 4 + 2][jjW] = wv1.z;
        Ws[(hsel + 1) * 4 + 3][jjW] = wv1.w;
        __syncthreads();
        if (h0 + 16 < H) {
            xv  = *(const float4*)(Xg + (size_t)(h0 + 16) * L);
            wv0 = *(const float4*)(Wg + h0 + 16 + (hsel + 0) * 4);
            wv1 = *(const float4*)(Wg + h0 + 16 + (hsel + 1) * 4);
        }
#pragma unroll
        for (int kk = 0; kk < 16; kk++) {
            ulonglong2 ap = *(const ulonglong2*)&Xs[kk][tl * 4];
            float4 wq = *(const float4*)&Ws[kk][tj * 4];
            ull w0 = pack2(wq.x, wq.x);
            ull w1 = pack2(wq.y, wq.y);
            ull w2 = pack2(wq.z, wq.z);
            ull w3 = pack2(wq.w, wq.w);
            ffma2(acc[0][0], w0, ap.x); ffma2(acc[0][1], w0, ap.y);
            ffma2(acc[1][0], w1, ap.x); ffma2(acc[1][1], w1, ap.y);
            ffma2(acc[2][0], w2, ap.x); ffma2(acc[2][1], w2, ap.y);
            ffma2(acc[3][0], w3, ap.x); ffma2(acc[3][1], w3, ap.y);
        }
        __syncthreads();
    }

    float4 bi = *(const float4*)(bias + j0 + tj * 4);
#pragma unroll
    for (int pp = 0; pp < 2; pp++) {
        float a0x, a0y, a1x, a1y, a2x, a2y, a3x, a3y;
        unpack2(acc[0][pp], a0x, a0y);
        unpack2(acc[1][pp], a1x, a1y);
        unpack2(acc[2][pp], a2x, a2y);
        unpack2(acc[3][pp], a3x, a3y);
        const int l = l0 + tl * 4 + pp * 2;
        float4 o0 = make_float4(a0x + bi.x, a1x + bi.y, a2x + bi.z, a3x + bi.w);
        float4 o1 = make_float4(a0y + bi.x, a1y + bi.y, a2y + bi.z, a3y + bi.w);
        *(float4*)(out + ((size_t)b * L + l    ) * JHD + j0 + tj * 4) = o0;
        *(float4*)(out + ((size_t)b * L + l + 1) * JHD + j0 + tj * 4) = o1;
    }
}

// ---------------- joint v3: scalar FFMA2, tuned for 4 warps/SMSP ----------------
// CTA 256 thr (8 warps), tile 16 t x 32 u. Thread: warp w -> t {2w, 2w+1}, lane -> u.
// smem floats: e[16][320] untransposed (broadcast reads), p swizzled [j][u^],
//              w [j][36].
#define JS_E (16 * JHD)
#define JS_P (32 * JHD)
#define JS_W (WST * JHD)
#define JS_TOTAL ((JS_E + JS_P + JS_W) * 4)

__global__ __launch_bounds__(256, 2) void joint_kernel(
    const float* __restrict__ e, const float* __restrict__ p,
    const float* __restrict__ wt, const float* __restrict__ bo,
    float* __restrict__ out)
{
    extern __shared__ float sm[];
    float* e_s = sm;                     // [t][j] 16 x 320
    float* p_s = sm + JS_E;              // [j][u^(j&31)]
    float* w_s = sm + JS_E + JS_P;       // [j][c] stride 36
    __shared__ float b_s[NC];

    const int tid  = threadIdx.x;
    const int wid  = tid >> 5;
    const int ul   = tid & 31;
    const int b    = blockIdx.z;
    const int tg   = blockIdx.y * 16;
    const int ublk = blockIdx.x;         // 0..3

    // load e (coalesced, straight copy)
    {
        const float* eb = e + ((size_t)b * TD + tg) * JHD;
        for (int idx = tid; idx < JS_E; idx += 256) e_s[idx] = eb[idx];
    }
    // load p with XOR-swizzled transpose (conflict-free store & read)
    {
        const float* pb = p + ((size_t)b * UD + ublk * 32) * JHD;
        for (int idx = tid; idx < JS_P; idx += 256) {
            int u = idx / JHD, j = idx - u * JHD;
            p_s[j * 32 + (u ^ (j & 31))] = pb[idx];
        }
    }
    // load w (coalesced, straight copy of pre-transposed table)
    for (int idx = tid; idx < JS_W; idx += 256) w_s[idx] = wt[idx];
    if (tid < NC) b_s[tid] = bo[tid];
    __syncthreads();

    const float* e0p = e_s + (2 * wid) * JHD;
    const float* e1p = e0p + JHD;

    ull acc0[17], acc1[17];
#pragma unroll
    for (int q = 0; q < 17; q++) { acc0[q] = 0ull; acc1[q] = 0ull; }

#pragma unroll 2
    for (int j = 0; j < JHD; j++) {
        float pv = p_s[j * 32 + (ul ^ (j & 31))];
        float ev0 = e0p[j];
        float ev1 = e1p[j];
        float h0 = fmaxf(ev0 + pv, 0.f);
        float h1 = fmaxf(ev1 + pv, 0.f);
        ull h0p = pack2(h0, h0);
        ull h1p = pack2(h1, h1);
        const ulonglong2* wr = (const ulonglong2*)(w_s + j * WST);
#pragma unroll
        for (int q = 0; q < 8; q++) {
            ulonglong2 w = wr[q];
            ffma2(acc0[2 * q    ], h0p, w.x);
            ffma2(acc0[2 * q + 1], h0p, w.y);
            ffma2(acc1[2 * q    ], h1p, w.x);
            ffma2(acc1[2 * q + 1], h1p, w.y);
        }
        ull wl = ((const ull*)(w_s + j * WST))[16];
        ffma2(acc0[16], h0p, wl);
        ffma2(acc1[16], h1p, wl);
    }

    // ---- epilogue: bias + log_softmax + store (2 rows per thread) ----
    const int u = ublk * 32 + ul;
#pragma unroll 1
    for (int r = 0; r < 2; r++) {
        const ull* acc = r ? acc1 : acc0;
        float lg[NC];
        float mx = -3.402823466e38f;
#pragma unroll
        for (int q = 0; q < 17; q++) {
            float x, y;
            unpack2(acc[q], x, y);
            x += b_s[2 * q];
            y += b_s[2 * q + 1];
            lg[2 * q] = x;
            lg[2 * q + 1] = y;
            mx = fmaxf(mx, fmaxf(x, y));
        }
        float s = 0.f;
#pragma unroll
        for (int c = 0; c < NC; c++) s += __expf(lg[c] - mx);
        const float lse = mx + __logf(s);
        const int t = tg + 2 * wid + r;
        float* op = out + (((size_t)b * TD + t) * UD + u) * NC;
#pragma unroll
        for (int q = 0; q < 17; q++)
            *(float2*)(op + 2 * q) = make_float2(lg[2 * q] - lse, lg[2 * q + 1] - lse);
    }
}

// ---------------- launch ----------------
extern "C" void kernel_launch(void* const* d_in, const int* in_sizes, int n_in,
                              void* d_out, int out_size)
{
    const float* enc    = (const float*)d_in[0];
    const float* dec    = (const float*)d_in[1];
    const float* W_enc  = (const float*)d_in[2];
    const float* b_enc  = (const float*)d_in[3];
    const float* W_pred = (const float*)d_in[4];
    const float* b_pred = (const float*)d_in[5];
    const float* W_out  = (const float*)d_in[6];
    const float* b_out  = (const float*)d_in[7];
    float* out = (float*)d_out;

    float *e_buf = nullptr, *p_buf = nullptr, *wt = nullptr;
    cudaGetSymbolAddress((void**)&e_buf, g_e);
    cudaGetSymbolAddress((void**)&p_buf, g_p);
    cudaGetSymbolAddress((void**)&wt, g_wt);

    cudaFuncSetAttribute(joint_kernel,
                         cudaFuncAttributeMaxDynamicSharedMemorySize, JS_TOTAL);

    prep_w_kernel<<<12, 960>>>(W_out);
    proj_all_kernel<<<dim3(20, 5, NB), 128>>>(enc, W_enc, b_enc,
                                              dec, W_pred, b_pred, e_buf, p_buf);
    // grid: 4 u-blocks x 32 t-blocks x 8 b = 1024 CTAs, 105KB smem, 2 CTAs/SM
    joint_kernel<<<dim3(UD / 32, TD / 16, NB), 256, JS_TOTAL>>>(
        e_buf, p_buf, wt, b_out, out);
}